// round 10
// baseline (speedup 1.0000x reference)
#include <cuda_runtime.h>

#define BB 64
#define TT 512
#define HH 768
#define LL 9
#define NG 10
#define LOG2E 1.4426950408889634f
#define LN2   0.6931471805599453f

__device__ __align__(16) float g_logits[BB * TT * LL];
__device__ float g_ll[BB];
__device__ float g_red[4];   // tp, tn, fp, corr
__device__ int   g_tick;     // completion ticket (zero-init; reset by last block)

__device__ __forceinline__ float ex2f_(float x) {
    float y; asm("ex2.approx.ftz.f32 %0, %1;" : "=f"(y) : "f"(x)); return y;
}
__device__ __forceinline__ float lg2f_(float x) {
    float y; asm("lg2.approx.ftz.f32 %0, %1;" : "=f"(y) : "f"(x)); return y;
}
__device__ __forceinline__ int wredi(int v) {
    #pragma unroll
    for (int o = 16; o; o >>= 1) v += __shfl_xor_sync(0xffffffffu, v, o);
    return v;
}
__device__ __forceinline__ float wredf(float v) {
    #pragma unroll
    for (int o = 16; o; o >>= 1) v += __shfl_xor_sync(0xffffffffu, v, o);
    return v;
}

#define MAP_IDENTITY 0x876543210ull
__device__ __forceinline__ unsigned long long map_compose(unsigned long long F,
                                                          unsigned long long G) {
    unsigned long long h = 0;
    #pragma unroll
    for (int i = 0; i < 9; i++) {
        int gi = (int)((G >> (4 * i)) & 15ull);
        unsigned long long fi = (F >> (gi * 4)) & 15ull;
        h |= fi << (4 * i);
    }
    return h;
}

struct CrfSmem {
    float slog[TT * LL];
    float astore[TT * LL];
    float swexp[TT * LL];
    float Ts[LL * LL];
    float sP[LL * LL];
    float sM[NG][LL][LL];
    int   sE[NG][LL];
    int   sEg[NG];
    unsigned char sbp[TT * LL];
    unsigned char stag[TT];
    float s_logZ;
    int   s_lasti;
    int   s_isLast;
};

// ---------------------------------------------------------------------------
// Kernel 1: logits = x@W + b (float4 x, packed fma.rn.f32x2). 1024 blocks.
// ---------------------------------------------------------------------------
__global__ void __launch_bounds__(256) gemm_kernel(const float* __restrict__ x,
                                                   const float* __restrict__ W,
                                                   const float* __restrict__ bias) {
    __shared__ __align__(16) float Ws[HH * 9];
    __shared__ float bs[LL];

    if (blockIdx.x == 0 && threadIdx.x < 4) g_red[threadIdx.x] = 0.0f;

    {
        const float4* src = (const float4*)W;
        float4* dst = (float4*)Ws;
        for (int i = threadIdx.x; i < HH * 9 / 4; i += 256) dst[i] = src[i];
    }
    if (threadIdx.x < LL) bs[threadIdx.x] = bias[threadIdx.x];
    __syncthreads();

    int warp = threadIdx.x >> 5, lane = threadIdx.x & 31;
    int row0 = (blockIdx.x * 8 + warp) * 4;
    const float* xp = x + (size_t)row0 * HH;

    unsigned long long acc[4][5];
    #pragma unroll
    for (int r = 0; r < 4; r++)
        #pragma unroll
        for (int p = 0; p < 5; p++) acc[r][p] = 0ull;

    #pragma unroll
    for (int kk = 0; kk < 6; kk++) {
        int h0 = lane * 4 + 128 * kk;
        float4 xr[4];
        xr[0] = *(const float4*)(xp + h0);
        xr[1] = *(const float4*)(xp + HH + h0);
        xr[2] = *(const float4*)(xp + 2 * HH + h0);
        xr[3] = *(const float4*)(xp + 3 * HH + h0);
        float wf[36];
        {
            const float4* wp = (const float4*)(Ws + h0 * 9);
            #pragma unroll
            for (int i = 0; i < 9; i++) ((float4*)wf)[i] = wp[i];
        }
        #pragma unroll
        for (int d = 0; d < 4; d++) {
            const float* wr = wf + 9 * d;
            unsigned long long w0, w1, w2, w3, w4p;
            asm("mov.b64 %0, {%1,%2};" : "=l"(w0) : "f"(wr[0]), "f"(wr[1]));
            asm("mov.b64 %0, {%1,%2};" : "=l"(w1) : "f"(wr[2]), "f"(wr[3]));
            asm("mov.b64 %0, {%1,%2};" : "=l"(w2) : "f"(wr[4]), "f"(wr[5]));
            asm("mov.b64 %0, {%1,%2};" : "=l"(w3) : "f"(wr[6]), "f"(wr[7]));
            asm("mov.b64 %0, {%1,%2};" : "=l"(w4p) : "f"(wr[8]), "f"(0.0f));
            #pragma unroll
            for (int r = 0; r < 4; r++) {
                float xv = (d == 0) ? xr[r].x : (d == 1) ? xr[r].y
                         : (d == 2) ? xr[r].z : xr[r].w;
                unsigned long long x2;
                asm("mov.b64 %0, {%1,%1};" : "=l"(x2) : "f"(xv));
                asm("fma.rn.f32x2 %0, %1, %2, %0;" : "+l"(acc[r][0]) : "l"(x2), "l"(w0));
                asm("fma.rn.f32x2 %0, %1, %2, %0;" : "+l"(acc[r][1]) : "l"(x2), "l"(w1));
                asm("fma.rn.f32x2 %0, %1, %2, %0;" : "+l"(acc[r][2]) : "l"(x2), "l"(w2));
                asm("fma.rn.f32x2 %0, %1, %2, %0;" : "+l"(acc[r][3]) : "l"(x2), "l"(w3));
                asm("fma.rn.f32x2 %0, %1, %2, %0;" : "+l"(acc[r][4]) : "l"(x2), "l"(w4p));
            }
        }
    }

    #pragma unroll
    for (int r = 0; r < 4; r++) {
        float a[9];
        #pragma unroll
        for (int p = 0; p < 4; p++) {
            float lo, hi;
            asm("mov.b64 {%0,%1}, %2;" : "=f"(lo), "=f"(hi) : "l"(acc[r][p]));
            a[2 * p] = lo; a[2 * p + 1] = hi;
        }
        { float lo, hi;
          asm("mov.b64 {%0,%1}, %2;" : "=f"(lo), "=f"(hi) : "l"(acc[r][4]));
          a[8] = lo; (void)hi; }
        #pragma unroll
        for (int l = 0; l < 9; l++) {
            float v = a[l];
            v += __shfl_xor_sync(0xffffffffu, v, 16);
            v += __shfl_xor_sync(0xffffffffu, v, 8);
            v += __shfl_xor_sync(0xffffffffu, v, 4);
            v += __shfl_xor_sync(0xffffffffu, v, 2);
            v += __shfl_xor_sync(0xffffffffu, v, 1);
            a[l] = v;
        }
        if (lane < LL)
            g_logits[(size_t)(row0 + r) * LL + lane] = a[lane] + bs[lane];
    }
}

// ---------------------------------------------------------------------------
// Kernel 2: per-batch CRF. Viterbi chain runs a FIXED 511 steps (compile-time
// trip count, unroll 8, no in-loop branch); rows >= sl are garbage but unused.
// ---------------------------------------------------------------------------
__global__ void __launch_bounds__(128) crf_kernel(const float* __restrict__ trans,
                                                  const int* __restrict__ label,
                                                  const int* __restrict__ seqlen,
                                                  float* __restrict__ outF) {
    extern __shared__ __align__(16) char smem_raw[];
    CrfSmem* S = (CrfSmem*)smem_raw;

    int b = blockIdx.x;
    int tid = threadIdx.x, lane = tid & 31, warp = tid >> 5;
    int sl = seqlen[b];

    // ---- stage logits -> slog + swexp; T, P=exp(T) ----
    {
        const float4* src = (const float4*)(g_logits + (size_t)b * TT * LL);
        float4* dst = (float4*)S->slog;
        float4* dwe = (float4*)S->swexp;
        for (int i = tid; i < TT * LL / 4; i += 128) {
            float4 v = src[i];
            dst[i] = v;
            float4 e;
            e.x = ex2f_(v.x * LOG2E); e.y = ex2f_(v.y * LOG2E);
            e.z = ex2f_(v.z * LOG2E); e.w = ex2f_(v.w * LOG2E);
            dwe[i] = e;
        }
        if (tid < LL * LL) {
            float t = trans[tid];
            S->Ts[tid] = t;
            S->sP[tid] = ex2f_(t * LOG2E);
        }
    }
    __syncthreads();

    int j = (lane < LL) ? lane : (LL - 1);

    if (warp == 0) {
        // ===== exact serial Viterbi: fixed 511 steps, branch-free body =====
        float Tj[9];
        #pragma unroll
        for (int i = 0; i < 9; i++) Tj[i] = S->Ts[i * LL + j];
        float a = S->slog[j];
        const float* lg = S->slog + j;     // logit[t][j] at lg[t*LL]
        float* ast = S->astore + j;        // lanes 9-31 alias state 8 (same value)
        ast[0] = a;

        #pragma unroll 8
        for (int t = 1; t < TT; t++) {
            float av0 = __shfl_sync(0xffffffffu, a, 0);
            float av1 = __shfl_sync(0xffffffffu, a, 1);
            float av2 = __shfl_sync(0xffffffffu, a, 2);
            float av3 = __shfl_sync(0xffffffffu, a, 3);
            float av4 = __shfl_sync(0xffffffffu, a, 4);
            float av5 = __shfl_sync(0xffffffffu, a, 5);
            float av6 = __shfl_sync(0xffffffffu, a, 6);
            float av7 = __shfl_sync(0xffffffffu, a, 7);
            float av8 = __shfl_sync(0xffffffffu, a, 8);
            float w = lg[t * LL];
            float m = fmaxf(fmaxf(fmaxf(av0 + Tj[0], av1 + Tj[1]),
                                  fmaxf(av2 + Tj[2], av3 + Tj[3])),
                            fmaxf(fmaxf(fmaxf(av4 + Tj[4], av5 + Tj[5]),
                                        fmaxf(av6 + Tj[6], av7 + Tj[7])),
                                  av8 + Tj[8]));
            a = m + w;
            ast[t * LL] = a;
        }
        // last = first-max argmax of alpha at the TRUE final step (sl-1)
        const float* af = S->astore + (sl - 1) * LL;
        float best = af[0];
        int last = 0;
        #pragma unroll
        for (int i = 1; i < 9; i++) {
            float v = af[i];
            if (v > best) { best = v; last = i; }
        }
        if (lane == 0) S->s_lasti = last;
    } else {
        // ================= chunk-parallel logZ =================
        int wl = tid - 32;
        int g = wl / 9, cj = wl - 9 * g;
        int NS = sl - 1;
        int Cs = (NS + NG - 1) / NG;
        int t0 = 1 + g * Cs;
        int t1 = min(t0 + Cs, sl);

        if (wl < 90) {
            float P[81];
            #pragma unroll
            for (int k = 0; k < 81; k++) P[k] = S->sP[k];

            float v[9];
            int E = 0;
            if (Cs > 0 && t0 < t1) {
                const float* w = S->swexp + t0 * LL;
                #pragma unroll
                for (int m = 0; m < 9; m++) v[m] = w[m] * P[cj * 9 + m];
                for (int t = t0 + 1; t < t1; t++) {
                    const float* wt = S->swexp + t * LL;
                    float nv[9];
                    #pragma unroll
                    for (int m = 0; m < 9; m++) {
                        float s = v[0] * P[m];
                        #pragma unroll
                        for (int i = 1; i < 9; i++) s = fmaf(v[i], P[i * 9 + m], s);
                        nv[m] = s * wt[m];
                    }
                    unsigned bits = __float_as_uint(nv[0]);
                    int e = (int)(bits >> 23) - 127;
                    E += e;
                    float factor = __uint_as_float((unsigned)(127 - e) << 23);
                    #pragma unroll
                    for (int m = 0; m < 9; m++) v[m] = nv[m] * factor;
                }
            } else {
                #pragma unroll
                for (int m = 0; m < 9; m++) v[m] = (m == cj) ? 1.0f : 0.0f;
                E = 0;
            }
            S->sE[g][cj] = E;
            #pragma unroll
            for (int m = 0; m < 9; m++) S->sM[g][m][cj] = v[m];
        }
        asm volatile("bar.sync 1, 96;" ::: "memory");
        if (wl < 90) {
            int Emax = S->sE[g][0];
            #pragma unroll
            for (int i = 1; i < 9; i++) Emax = max(Emax, S->sE[g][i]);
            int E = S->sE[g][cj];
            int d = E - Emax;
            float adj = (d < -120) ? 0.0f : __uint_as_float((unsigned)(127 + d) << 23);
            #pragma unroll
            for (int m = 0; m < 9; m++) S->sM[g][m][cj] *= adj;
            if (cj == 0) S->sEg[g] = Emax;
        }
        asm volatile("bar.sync 1, 96;" ::: "memory");

        if (warp == 1) {
            float p0 = S->slog[0] * LOG2E;
            float alpha = ex2f_(S->slog[j] * LOG2E - p0);
            int A = 0;
            for (int g2 = 0; g2 < NG; g2++) {
                float av2[9];
                #pragma unroll
                for (int i = 0; i < 9; i++) av2[i] = __shfl_sync(0xffffffffu, alpha, i);
                float s = S->sM[g2][j][0] * av2[0];
                #pragma unroll
                for (int i2 = 1; i2 < 9; i2++)
                    s = fmaf(S->sM[g2][j][i2], av2[i2], s);
                float s0 = __shfl_sync(0xffffffffu, s, 0);
                unsigned bits = __float_as_uint(s0);
                int e = (int)(bits >> 23) - 127;
                A += e + S->sEg[g2];
                float factor = __uint_as_float((unsigned)(127 - e) << 23);
                alpha = s * factor;
            }
            float cv[9];
            #pragma unroll
            for (int i = 0; i < 9; i++) cv[i] = __shfl_sync(0xffffffffu, alpha, i);
            float sum = ((cv[0] + cv[1]) + (cv[2] + cv[3]))
                      + (((cv[4] + cv[5]) + (cv[6] + cv[7])) + cv[8]);
            float logZ = (lg2f_(sum) + (float)A + p0) * LN2;
            if (lane == 0) S->s_logZ = logZ;
            __syncwarp();

            const int* lab = label + b * TT;
            float sc = 0.0f;
            for (int t = lane; t < sl; t += 32) {
                int lt = lab[t];
                sc += S->slog[t * LL + lt];
                if (t > 0) sc += S->Ts[lab[t - 1] * LL + lt];
            }
            sc = wredf(sc);
            if (lane == 0) g_ll[b] = S->s_logZ - sc;
        }
    }
    __syncthreads();

    // ---- parallel backpointer recompute (rows t < sl only) ----
    if (tid < 126) {
        int jj = tid % 9, g = tid / 9;
        float Tc[9];
        #pragma unroll
        for (int i = 0; i < 9; i++) Tc[i] = S->Ts[i * LL + jj];
        for (int t = 1 + g; t < sl; t += 14) {
            const float* ap = S->astore + (t - 1) * LL;
            float bv = ap[0] + Tc[0];
            int bi = 0;
            #pragma unroll
            for (int i = 1; i < 9; i++) {
                float v = ap[i] + Tc[i];
                if (v > bv) { bv = v; bi = i; }
            }
            S->sbp[t * LL + jj] = (unsigned char)bi;
        }
    }
    __syncthreads();

    int last = S->s_lasti;
    for (int t = sl - 1 + tid; t < TT; t += 128) S->stag[t] = (unsigned char)last;

    // ---- parallel backtrace via map suffix-scan (warp 0) ----
    if (warp == 0 && sl > 1) {
        int N = sl - 1;
        int C = (N + 31) >> 5;
        int a0 = 1 + lane * C;
        int b0 = min(a0 + C, sl);
        unsigned long long Pm = MAP_IDENTITY;
        for (int m = a0; m < b0; m++) {
            const unsigned char* row = S->sbp + m * LL;
            unsigned long long f = 0;
            #pragma unroll
            for (int i = 0; i < 9; i++)
                f |= (unsigned long long)row[i] << (4 * i);
            Pm = map_compose(Pm, f);
        }
        #pragma unroll
        for (int off = 1; off < 32; off <<= 1) {
            unsigned long long q = __shfl_down_sync(0xffffffffu, Pm, off);
            if (lane + off < 32) Pm = map_compose(Pm, q);
        }
        unsigned long long R = __shfl_down_sync(0xffffffffu, Pm, 1);
        if (lane == 31) R = MAP_IDENTITY;
        if (a0 < sl) {
            int xcur = (int)((R >> (4 * last)) & 15ull);
            for (int m = b0 - 1; m >= a0; m--) {
                xcur = S->sbp[m * LL + xcur];
                S->stag[m - 1] = (unsigned char)xcur;
            }
        }
    }
    __syncthreads();

    // ---- vit output + fused metrics ----
    float* vout = outF + b * TT;
    const int* lab = label + b * TT;
    int tp = 0, tn = 0, fp = 0, corr = 0;
    for (int i = tid; i < TT; i += 128) {
        int vi = S->stag[i];
        vout[i] = (float)vi;
        int la = lab[i];
        if (la > 0) { if (vi == la) tp++; else tn++; }   // unmasked, per reference
        if (i < sl) {
            if (vi == la) corr++;
            if (la == 0 && vi > 0) fp++;
        }
    }
    tp = wredi(tp); tn = wredi(tn); fp = wredi(fp); corr = wredi(corr);
    if (lane == 0) {
        atomicAdd(&g_red[0], (float)tp);
        atomicAdd(&g_red[1], (float)tn);
        atomicAdd(&g_red[2], (float)fp);
        atomicAdd(&g_red[3], (float)corr);
    }

    // ---- completion ticket; last block writes scalars ----
    __threadfence();
    __syncthreads();
    if (tid == 0) {
        int old = atomicAdd(&g_tick, 1);
        S->s_isLast = (old == BB - 1);
    }
    __syncthreads();
    if (S->s_isLast && warp == 0) {
        __threadfence();
        float lsum = g_ll[lane] + g_ll[lane + 32];
        int sls = seqlen[lane] + seqlen[lane + 32];
        lsum = wredf(lsum);
        sls = wredi(sls);
        if (lane == 0) {
            outF[BB * TT + 0] = g_red[0];                 // tp
            outF[BB * TT + 1] = g_red[1];                 // tn
            outF[BB * TT + 2] = g_red[2];                 // fp
            outF[BB * TT + 3] = lsum / (float)BB;         // loss
            outF[BB * TT + 4] = g_red[3] / (float)sls;    // accuracy
            g_tick = 0;                                   // reset for replay
        }
    }
}

// ---------------------------------------------------------------------------
extern "C" void kernel_launch(void* const* d_in, const int* in_sizes, int n_in,
                              void* d_out, int out_size) {
    const float* x      = (const float*)d_in[0];
    const float* W      = (const float*)d_in[1];
    const float* bias   = (const float*)d_in[2];
    const float* trans  = (const float*)d_in[3];
    const int*   label  = (const int*)d_in[4];
    const int*   seqlen = (const int*)d_in[5];
    float* out = (float*)d_out;

    static int smem_set = 0;
    if (!smem_set) {
        cudaFuncSetAttribute(crf_kernel,
                             cudaFuncAttributeMaxDynamicSharedMemorySize,
                             (int)sizeof(CrfSmem));
        smem_set = 1;
    }

    gemm_kernel<<<1024, 256>>>(x, W, bias);
    crf_kernel<<<BB, 128, sizeof(CrfSmem)>>>(trans, label, seqlen, out);
}

// round 11
// speedup vs baseline: 1.0731x; 1.0731x over previous
#include <cuda_runtime.h>

#define BB 64
#define TT 512
#define HH 768
#define LL 9
#define AST 12   // astore row stride (floats): 48B, 16B-aligned rows
#define NG 10
#define LOG2E 1.4426950408889634f
#define LN2   0.6931471805599453f

__device__ __align__(16) float g_logits[BB * TT * LL];
__device__ float g_ll[BB];
__device__ float g_red[4];   // tp, tn, fp, corr
__device__ int   g_tick;     // completion ticket (zero-init; reset by last block)

__device__ __forceinline__ float ex2f_(float x) {
    float y; asm("ex2.approx.ftz.f32 %0, %1;" : "=f"(y) : "f"(x)); return y;
}
__device__ __forceinline__ float lg2f_(float x) {
    float y; asm("lg2.approx.ftz.f32 %0, %1;" : "=f"(y) : "f"(x)); return y;
}
__device__ __forceinline__ int wredi(int v) {
    #pragma unroll
    for (int o = 16; o; o >>= 1) v += __shfl_xor_sync(0xffffffffu, v, o);
    return v;
}
__device__ __forceinline__ float wredf(float v) {
    #pragma unroll
    for (int o = 16; o; o >>= 1) v += __shfl_xor_sync(0xffffffffu, v, o);
    return v;
}

#define MAP_IDENTITY 0x876543210ull
__device__ __forceinline__ unsigned long long map_compose(unsigned long long F,
                                                          unsigned long long G) {
    unsigned long long h = 0;
    #pragma unroll
    for (int i = 0; i < 9; i++) {
        int gi = (int)((G >> (4 * i)) & 15ull);
        unsigned long long fi = (F >> (gi * 4)) & 15ull;
        h |= fi << (4 * i);
    }
    return h;
}

struct CrfSmem {
    float slog[TT * LL];
    float astore[TT * AST];       // stride-12 rows, 16B-aligned
    float swexp[TT * LL];
    float Ts[LL * LL];
    float sP[LL * LL];
    float sM[NG][LL][LL];
    int   sE[NG][LL];
    int   sEg[NG];
    unsigned char sbp[TT * LL];
    unsigned char stag[TT];
    float s_logZ;
    int   s_lasti;
    int   s_isLast;
};

// ---------------------------------------------------------------------------
// Kernel 1: logits = x@W + b (float4 x, packed fma.rn.f32x2). 1024 blocks.
// ---------------------------------------------------------------------------
__global__ void __launch_bounds__(256) gemm_kernel(const float* __restrict__ x,
                                                   const float* __restrict__ W,
                                                   const float* __restrict__ bias) {
    __shared__ __align__(16) float Ws[HH * 9];
    __shared__ float bs[LL];

    if (blockIdx.x == 0 && threadIdx.x < 4) g_red[threadIdx.x] = 0.0f;

    {
        const float4* src = (const float4*)W;
        float4* dst = (float4*)Ws;
        for (int i = threadIdx.x; i < HH * 9 / 4; i += 256) dst[i] = src[i];
    }
    if (threadIdx.x < LL) bs[threadIdx.x] = bias[threadIdx.x];
    __syncthreads();

    int warp = threadIdx.x >> 5, lane = threadIdx.x & 31;
    int row0 = (blockIdx.x * 8 + warp) * 4;
    const float* xp = x + (size_t)row0 * HH;

    unsigned long long acc[4][5];
    #pragma unroll
    for (int r = 0; r < 4; r++)
        #pragma unroll
        for (int p = 0; p < 5; p++) acc[r][p] = 0ull;

    #pragma unroll
    for (int kk = 0; kk < 6; kk++) {
        int h0 = lane * 4 + 128 * kk;
        float4 xr[4];
        xr[0] = *(const float4*)(xp + h0);
        xr[1] = *(const float4*)(xp + HH + h0);
        xr[2] = *(const float4*)(xp + 2 * HH + h0);
        xr[3] = *(const float4*)(xp + 3 * HH + h0);
        float wf[36];
        {
            const float4* wp = (const float4*)(Ws + h0 * 9);
            #pragma unroll
            for (int i = 0; i < 9; i++) ((float4*)wf)[i] = wp[i];
        }
        #pragma unroll
        for (int d = 0; d < 4; d++) {
            const float* wr = wf + 9 * d;
            unsigned long long w0, w1, w2, w3, w4p;
            asm("mov.b64 %0, {%1,%2};" : "=l"(w0) : "f"(wr[0]), "f"(wr[1]));
            asm("mov.b64 %0, {%1,%2};" : "=l"(w1) : "f"(wr[2]), "f"(wr[3]));
            asm("mov.b64 %0, {%1,%2};" : "=l"(w2) : "f"(wr[4]), "f"(wr[5]));
            asm("mov.b64 %0, {%1,%2};" : "=l"(w3) : "f"(wr[6]), "f"(wr[7]));
            asm("mov.b64 %0, {%1,%2};" : "=l"(w4p) : "f"(wr[8]), "f"(0.0f));
            #pragma unroll
            for (int r = 0; r < 4; r++) {
                float xv = (d == 0) ? xr[r].x : (d == 1) ? xr[r].y
                         : (d == 2) ? xr[r].z : xr[r].w;
                unsigned long long x2;
                asm("mov.b64 %0, {%1,%1};" : "=l"(x2) : "f"(xv));
                asm("fma.rn.f32x2 %0, %1, %2, %0;" : "+l"(acc[r][0]) : "l"(x2), "l"(w0));
                asm("fma.rn.f32x2 %0, %1, %2, %0;" : "+l"(acc[r][1]) : "l"(x2), "l"(w1));
                asm("fma.rn.f32x2 %0, %1, %2, %0;" : "+l"(acc[r][2]) : "l"(x2), "l"(w2));
                asm("fma.rn.f32x2 %0, %1, %2, %0;" : "+l"(acc[r][3]) : "l"(x2), "l"(w3));
                asm("fma.rn.f32x2 %0, %1, %2, %0;" : "+l"(acc[r][4]) : "l"(x2), "l"(w4p));
            }
        }
    }

    #pragma unroll
    for (int r = 0; r < 4; r++) {
        float a[9];
        #pragma unroll
        for (int p = 0; p < 4; p++) {
            float lo, hi;
            asm("mov.b64 {%0,%1}, %2;" : "=f"(lo), "=f"(hi) : "l"(acc[r][p]));
            a[2 * p] = lo; a[2 * p + 1] = hi;
        }
        { float lo, hi;
          asm("mov.b64 {%0,%1}, %2;" : "=f"(lo), "=f"(hi) : "l"(acc[r][4]));
          a[8] = lo; (void)hi; }
        #pragma unroll
        for (int l = 0; l < 9; l++) {
            float v = a[l];
            v += __shfl_xor_sync(0xffffffffu, v, 16);
            v += __shfl_xor_sync(0xffffffffu, v, 8);
            v += __shfl_xor_sync(0xffffffffu, v, 4);
            v += __shfl_xor_sync(0xffffffffu, v, 2);
            v += __shfl_xor_sync(0xffffffffu, v, 1);
            a[l] = v;
        }
        if (lane < LL)
            g_logits[(size_t)(row0 + r) * LL + lane] = a[lane] + bs[lane];
    }
}

// ---------------------------------------------------------------------------
// Kernel 2: per-batch CRF. Viterbi chain broadcasts alpha through the astore
// smem row itself (2xLDS.128 + LDS.32, broadcast) instead of 9 SHFLs.
// ---------------------------------------------------------------------------
__global__ void __launch_bounds__(128) crf_kernel(const float* __restrict__ trans,
                                                  const int* __restrict__ label,
                                                  const int* __restrict__ seqlen,
                                                  float* __restrict__ outF) {
    extern __shared__ __align__(16) char smem_raw[];
    CrfSmem* S = (CrfSmem*)smem_raw;

    int b = blockIdx.x;
    int tid = threadIdx.x, lane = tid & 31, warp = tid >> 5;
    int sl = seqlen[b];

    // ---- stage logits -> slog + swexp; T, P=exp(T) ----
    {
        const float4* src = (const float4*)(g_logits + (size_t)b * TT * LL);
        float4* dst = (float4*)S->slog;
        float4* dwe = (float4*)S->swexp;
        for (int i = tid; i < TT * LL / 4; i += 128) {
            float4 v = src[i];
            dst[i] = v;
            float4 e;
            e.x = ex2f_(v.x * LOG2E); e.y = ex2f_(v.y * LOG2E);
            e.z = ex2f_(v.z * LOG2E); e.w = ex2f_(v.w * LOG2E);
            dwe[i] = e;
        }
        if (tid < LL * LL) {
            float t = trans[tid];
            S->Ts[tid] = t;
            S->sP[tid] = ex2f_(t * LOG2E);
        }
    }
    __syncthreads();

    int j = (lane < LL) ? lane : (LL - 1);

    if (warp == 0) {
        // ===== exact serial Viterbi via smem-row broadcast =====
        float Tj[9];
        #pragma unroll
        for (int i = 0; i < 9; i++) Tj[i] = S->Ts[i * LL + j];
        // t = 0: write initial row (lanes 9-31 alias state 8, same value)
        S->astore[j] = S->slog[j];
        const float* lg = S->slog + j;

        #pragma unroll 4
        for (int t = 1; t < TT; t++) {
            const float* prow = S->astore + (t - 1) * AST;   // same addr all lanes
            float4 r0 = *(const float4*)(prow);              // a[0..3]
            float4 r1 = *(const float4*)(prow + 4);          // a[4..7]
            float  a8 = prow[8];
            float w = lg[t * LL];
            float m = fmaxf(fmaxf(fmaxf(r0.x + Tj[0], r0.y + Tj[1]),
                                  fmaxf(r0.z + Tj[2], r0.w + Tj[3])),
                            fmaxf(fmaxf(fmaxf(r1.x + Tj[4], r1.y + Tj[5]),
                                        fmaxf(r1.z + Tj[6], r1.w + Tj[7])),
                                  a8 + Tj[8]));
            S->astore[t * AST + j] = m + w;
        }
        // last = first-max argmax of alpha at the TRUE final step (sl-1)
        const float* af = S->astore + (sl - 1) * AST;
        float best = af[0];
        int last = 0;
        #pragma unroll
        for (int i = 1; i < 9; i++) {
            float v = af[i];
            if (v > best) { best = v; last = i; }
        }
        if (lane == 0) S->s_lasti = last;
    } else {
        // ================= chunk-parallel logZ =================
        int wl = tid - 32;
        int g = wl / 9, cj = wl - 9 * g;
        int NS = sl - 1;
        int Cs = (NS + NG - 1) / NG;
        int t0 = 1 + g * Cs;
        int t1 = min(t0 + Cs, sl);

        if (wl < 90) {
            float P[81];
            #pragma unroll
            for (int k = 0; k < 81; k++) P[k] = S->sP[k];

            float v[9];
            int E = 0;
            if (Cs > 0 && t0 < t1) {
                const float* w = S->swexp + t0 * LL;
                #pragma unroll
                for (int m = 0; m < 9; m++) v[m] = w[m] * P[cj * 9 + m];
                for (int t = t0 + 1; t < t1; t++) {
                    const float* wt = S->swexp + t * LL;
                    float nv[9];
                    #pragma unroll
                    for (int m = 0; m < 9; m++) {
                        float s = v[0] * P[m];
                        #pragma unroll
                        for (int i = 1; i < 9; i++) s = fmaf(v[i], P[i * 9 + m], s);
                        nv[m] = s * wt[m];
                    }
                    unsigned bits = __float_as_uint(nv[0]);
                    int e = (int)(bits >> 23) - 127;
                    E += e;
                    float factor = __uint_as_float((unsigned)(127 - e) << 23);
                    #pragma unroll
                    for (int m = 0; m < 9; m++) v[m] = nv[m] * factor;
                }
            } else {
                #pragma unroll
                for (int m = 0; m < 9; m++) v[m] = (m == cj) ? 1.0f : 0.0f;
                E = 0;
            }
            S->sE[g][cj] = E;
            #pragma unroll
            for (int m = 0; m < 9; m++) S->sM[g][m][cj] = v[m];
        }
        asm volatile("bar.sync 1, 96;" ::: "memory");
        if (wl < 90) {
            int Emax = S->sE[g][0];
            #pragma unroll
            for (int i = 1; i < 9; i++) Emax = max(Emax, S->sE[g][i]);
            int E = S->sE[g][cj];
            int d = E - Emax;
            float adj = (d < -120) ? 0.0f : __uint_as_float((unsigned)(127 + d) << 23);
            #pragma unroll
            for (int m = 0; m < 9; m++) S->sM[g][m][cj] *= adj;
            if (cj == 0) S->sEg[g] = Emax;
        }
        asm volatile("bar.sync 1, 96;" ::: "memory");

        if (warp == 1) {
            float p0 = S->slog[0] * LOG2E;
            float alpha = ex2f_(S->slog[j] * LOG2E - p0);
            int A = 0;
            for (int g2 = 0; g2 < NG; g2++) {
                float av2[9];
                #pragma unroll
                for (int i = 0; i < 9; i++) av2[i] = __shfl_sync(0xffffffffu, alpha, i);
                float s = S->sM[g2][j][0] * av2[0];
                #pragma unroll
                for (int i2 = 1; i2 < 9; i2++)
                    s = fmaf(S->sM[g2][j][i2], av2[i2], s);
                float s0 = __shfl_sync(0xffffffffu, s, 0);
                unsigned bits = __float_as_uint(s0);
                int e = (int)(bits >> 23) - 127;
                A += e + S->sEg[g2];
                float factor = __uint_as_float((unsigned)(127 - e) << 23);
                alpha = s * factor;
            }
            float cv[9];
            #pragma unroll
            for (int i = 0; i < 9; i++) cv[i] = __shfl_sync(0xffffffffu, alpha, i);
            float sum = ((cv[0] + cv[1]) + (cv[2] + cv[3]))
                      + (((cv[4] + cv[5]) + (cv[6] + cv[7])) + cv[8]);
            float logZ = (lg2f_(sum) + (float)A + p0) * LN2;
            if (lane == 0) S->s_logZ = logZ;
            __syncwarp();

            const int* lab = label + b * TT;
            float sc = 0.0f;
            for (int t = lane; t < sl; t += 32) {
                int lt = lab[t];
                sc += S->slog[t * LL + lt];
                if (t > 0) sc += S->Ts[lab[t - 1] * LL + lt];
            }
            sc = wredf(sc);
            if (lane == 0) g_ll[b] = S->s_logZ - sc;
        }
    }
    __syncthreads();

    // ---- parallel backpointer recompute (rows t < sl only) ----
    if (tid < 126) {
        int jj = tid % 9, g = tid / 9;
        float Tc[9];
        #pragma unroll
        for (int i = 0; i < 9; i++) Tc[i] = S->Ts[i * LL + jj];
        for (int t = 1 + g; t < sl; t += 14) {
            const float* ap = S->astore + (t - 1) * AST;
            float bv = ap[0] + Tc[0];
            int bi = 0;
            #pragma unroll
            for (int i = 1; i < 9; i++) {
                float v = ap[i] + Tc[i];
                if (v > bv) { bv = v; bi = i; }
            }
            S->sbp[t * LL + jj] = (unsigned char)bi;
        }
    }
    __syncthreads();

    int last = S->s_lasti;
    for (int t = sl - 1 + tid; t < TT; t += 128) S->stag[t] = (unsigned char)last;

    // ---- parallel backtrace via map suffix-scan (warp 0) ----
    if (warp == 0 && sl > 1) {
        int N = sl - 1;
        int C = (N + 31) >> 5;
        int a0 = 1 + lane * C;
        int b0 = min(a0 + C, sl);
        unsigned long long Pm = MAP_IDENTITY;
        for (int m = a0; m < b0; m++) {
            const unsigned char* row = S->sbp + m * LL;
            unsigned long long f = 0;
            #pragma unroll
            for (int i = 0; i < 9; i++)
                f |= (unsigned long long)row[i] << (4 * i);
            Pm = map_compose(Pm, f);
        }
        #pragma unroll
        for (int off = 1; off < 32; off <<= 1) {
            unsigned long long q = __shfl_down_sync(0xffffffffu, Pm, off);
            if (lane + off < 32) Pm = map_compose(Pm, q);
        }
        unsigned long long R = __shfl_down_sync(0xffffffffu, Pm, 1);
        if (lane == 31) R = MAP_IDENTITY;
        if (a0 < sl) {
            int xcur = (int)((R >> (4 * last)) & 15ull);
            for (int m = b0 - 1; m >= a0; m--) {
                xcur = S->sbp[m * LL + xcur];
                S->stag[m - 1] = (unsigned char)xcur;
            }
        }
    }
    __syncthreads();

    // ---- vit output + fused metrics ----
    float* vout = outF + b * TT;
    const int* lab = label + b * TT;
    int tp = 0, tn = 0, fp = 0, corr = 0;
    for (int i = tid; i < TT; i += 128) {
        int vi = S->stag[i];
        vout[i] = (float)vi;
        int la = lab[i];
        if (la > 0) { if (vi == la) tp++; else tn++; }   // unmasked, per reference
        if (i < sl) {
            if (vi == la) corr++;
            if (la == 0 && vi > 0) fp++;
        }
    }
    tp = wredi(tp); tn = wredi(tn); fp = wredi(fp); corr = wredi(corr);
    if (lane == 0) {
        atomicAdd(&g_red[0], (float)tp);
        atomicAdd(&g_red[1], (float)tn);
        atomicAdd(&g_red[2], (float)fp);
        atomicAdd(&g_red[3], (float)corr);
    }

    // ---- completion ticket; last block writes scalars ----
    __threadfence();
    __syncthreads();
    if (tid == 0) {
        int old = atomicAdd(&g_tick, 1);
        S->s_isLast = (old == BB - 1);
    }
    __syncthreads();
    if (S->s_isLast && warp == 0) {
        __threadfence();
        float lsum = g_ll[lane] + g_ll[lane + 32];
        int sls = seqlen[lane] + seqlen[lane + 32];
        lsum = wredf(lsum);
        sls = wredi(sls);
        if (lane == 0) {
            outF[BB * TT + 0] = g_red[0];                 // tp
            outF[BB * TT + 1] = g_red[1];                 // tn
            outF[BB * TT + 2] = g_red[2];                 // fp
            outF[BB * TT + 3] = lsum / (float)BB;         // loss
            outF[BB * TT + 4] = g_red[3] / (float)sls;    // accuracy
            g_tick = 0;                                   // reset for replay
        }
    }
}

// ---------------------------------------------------------------------------
extern "C" void kernel_launch(void* const* d_in, const int* in_sizes, int n_in,
                              void* d_out, int out_size) {
    const float* x      = (const float*)d_in[0];
    const float* W      = (const float*)d_in[1];
    const float* bias   = (const float*)d_in[2];
    const float* trans  = (const float*)d_in[3];
    const int*   label  = (const int*)d_in[4];
    const int*   seqlen = (const int*)d_in[5];
    float* out = (float*)d_out;

    static int smem_set = 0;
    if (!smem_set) {
        cudaFuncSetAttribute(crf_kernel,
                             cudaFuncAttributeMaxDynamicSharedMemorySize,
                             (int)sizeof(CrfSmem));
        smem_set = 1;
    }

    gemm_kernel<<<1024, 256>>>(x, W, bias);
    crf_kernel<<<BB, 128, sizeof(CrfSmem)>>>(trans, label, seqlen, out);
}